// round 15
// baseline (speedup 1.0000x reference)
#include <cuda_runtime.h>
#include <cuda_fp16.h>
#include <math.h>
#include <stdint.h>

#define T_TOK 2048
#define DIM   1024
#define INTER 512
#define NEXP  16
#define TOPK  4
#define NGRP  4
#define GSZ   4
#define NE1   (NEXP + 1)

#define STG_BYTES 32768
#define SMEM_BYTES (3 * STG_BYTES)

#define WBIG  ((size_t)NEXP * INTER * DIM)
#define WSML  ((size_t)INTER * DIM)

#define NPROD (16 * 8 * NE1)   // ffn_out producer blocks = 2176

// ---------------- scratch ----------------
__device__ int           g_cnt[NEXP];    // zeroed at end of each call by riders
__device__ int           g_done;         // reset by prep each call
__device__ int           g_tok[NEXP][T_TOK];
__device__ unsigned char g_slot[NEXP][T_TOK];
__device__ float         g_wt[NEXP][T_TOK];
__device__ __half        g_xrh[(size_t)T_TOK * DIM];
__device__ __half        g_acth[(size_t)NE1 * T_TOK * INTER];
__device__ float         g_ybuf[TOPK][(size_t)T_TOK * DIM];
__device__ __half        g_w1h[WBIG + WSML];
__device__ __half        g_w3h[WBIG + WSML];
__device__ __half        g_w2h[WBIG + WSML];

// ---------------- helpers ----------------
__device__ __forceinline__ uint32_t smem_u32(const void* p) {
    uint32_t a;
    asm("{ .reg .u64 t; cvta.to.shared.u64 t, %1; cvt.u32.u64 %0, t; }" : "=r"(a) : "l"(p));
    return a;
}
__device__ __forceinline__ void cp16(uint32_t dst, const void* src) {
    asm volatile("cp.async.cg.shared.global [%0], [%1], 16;" :: "r"(dst), "l"(src));
}
#define CP_COMMIT() asm volatile("cp.async.commit_group;")
#define CP_WAIT1()  asm volatile("cp.async.wait_group 1;")

__device__ __forceinline__ void ldsm4(uint32_t* r, uint32_t addr) {
    asm volatile("ldmatrix.sync.aligned.m8n8.x4.shared.b16 {%0,%1,%2,%3}, [%4];"
                 : "=r"(r[0]), "=r"(r[1]), "=r"(r[2]), "=r"(r[3]) : "r"(addr));
}
__device__ __forceinline__ void mma_f16(float* d, const uint32_t* a, uint32_t b0, uint32_t b1) {
    asm volatile(
        "mma.sync.aligned.m16n8k16.row.col.f32.f16.f16.f32 "
        "{%0,%1,%2,%3}, {%4,%5,%6,%7}, {%8,%9}, {%0,%1,%2,%3};"
        : "+f"(d[0]), "+f"(d[1]), "+f"(d[2]), "+f"(d[3])
        : "r"(a[0]), "r"(a[1]), "r"(a[2]), "r"(a[3]), "r"(b0), "r"(b1));
}

// convert 8 fp32 -> 8 fp16 (vectorized)
__device__ __forceinline__ void cvt8(const float* src, __half* dst, size_t i) {
    float4 a = *(const float4*)(src + i);
    float4 b = *(const float4*)(src + i + 4);
    __half2 h0 = __floats2half2_rn(a.x, a.y), h1 = __floats2half2_rn(a.z, a.w);
    __half2 h2 = __floats2half2_rn(b.x, b.y), h3 = __floats2half2_rn(b.z, b.w);
    uint4 o;
    o.x = *(uint32_t*)&h0; o.y = *(uint32_t*)&h1;
    o.z = *(uint32_t*)&h2; o.w = *(uint32_t*)&h3;
    *(uint4*)(dst + i) = o;
}

// ---------------- prep: gate (blocks 0-255) + convert w1/w3/ws1/ws3 ----------------
__global__ __launch_bounds__(256) void prep_kernel(
    const float* __restrict__ x, const float* __restrict__ gw,
    const float* __restrict__ gbias,
    const float* __restrict__ w1, const float* __restrict__ w3,
    const float* __restrict__ ws1, const float* __restrict__ ws3)
{
    const int bid = blockIdx.x;
    if (bid == 0 && threadIdx.x == 0) g_done = 0;   // reset fusion counter for this call
    if (bid >= 256) {
        int idx = bid - 256;
        const float* src; __half* dst;
        if (idx < 4096)      { src = w1;  dst = g_w1h; }
        else if (idx < 8192) { src = w3;  dst = g_w3h;        idx -= 4096; }
        else if (idx < 8448) { src = ws1; dst = g_w1h + WBIG; idx -= 8192; }
        else                 { src = ws3; dst = g_w3h + WBIG; idx -= 8448; }
        size_t i = (size_t)idx * 2048 + (size_t)threadIdx.x * 8;
        cvt8(src, dst, i);
        return;
    }

    // ---- gate: 1 warp per token ----
    int t    = bid * 8 + (threadIdx.x >> 5);
    int lane = threadIdx.x & 31;

    float4 xr[8];
    const float4* xp = (const float4*)(x + (size_t)t * DIM) + lane;
#pragma unroll
    for (int i = 0; i < 8; i++) xr[i] = xp[i * 32];

    __half* xo = g_xrh + (size_t)t * DIM + lane * 4;
#pragma unroll
    for (int i = 0; i < 8; i++) {
        __half2 lo = __floats2half2_rn(xr[i].x, xr[i].y);
        __half2 hi = __floats2half2_rn(xr[i].z, xr[i].w);
        uint2 u;
        u.x = *(uint32_t*)&lo; u.y = *(uint32_t*)&hi;
        *(uint2*)(xo + i * 128) = u;
    }

    float sc[NEXP];
#pragma unroll
    for (int e = 0; e < NEXP; e++) {
        const float4* w = (const float4*)(gw + (size_t)e * DIM) + lane;
        float acc = 0.f;
#pragma unroll
        for (int i = 0; i < 8; i++) {
            float4 wv = w[i * 32];
            acc += xr[i].x * wv.x + xr[i].y * wv.y + xr[i].z * wv.z + xr[i].w * wv.w;
        }
#pragma unroll
        for (int o = 16; o > 0; o >>= 1) acc += __shfl_xor_sync(0xffffffffu, acc, o);
        sc[e] = 1.f / (1.f + __expf(-acc));
    }
    if (lane == 0) {
        float s[NEXP];
#pragma unroll
        for (int e = 0; e < NEXP; e++) s[e] = sc[e] + gbias[e];
        float gm[NGRP];
#pragma unroll
        for (int g = 0; g < NGRP; g++) {
            float m = s[g * GSZ];
#pragma unroll
            for (int j = 1; j < GSZ; j++) m = fmaxf(m, s[g * GSZ + j]);
            gm[g] = m;
        }
        int g1 = 0;
#pragma unroll
        for (int g = 1; g < NGRP; g++) if (gm[g] > gm[g1]) g1 = g;
        int g2 = -1;
#pragma unroll
        for (int g = 0; g < NGRP; g++) {
            if (g == g1) continue;
            if (g2 < 0 || gm[g] > gm[g2]) g2 = g;
        }
        float sm[NEXP];
#pragma unroll
        for (int e = 0; e < NEXP; e++) {
            int g = e / GSZ;
            sm[e] = (g == g1 || g == g2) ? s[e] : -1e30f;
        }
#pragma unroll
        for (int k = 0; k < TOPK; k++) {
            int best = 0; float bv = -1e38f;
#pragma unroll
            for (int e = 0; e < NEXP; e++) if (sm[e] > bv) { bv = sm[e]; best = e; }
            sm[best] = -1e38f;
            int pos = atomicAdd(&g_cnt[best], 1);
            g_tok[best][pos]  = t;
            g_slot[best][pos] = (unsigned char)k;
            g_wt[best][pos]   = sc[best];
        }
    }
}

#define FILL_ROW(stageu, R, srcp) do {                                        \
        uint32_t _rb = (stageu) + (uint32_t)(R) * 128;                        \
        int _e7 = (R) & 7;                                                    \
        cp16(_rb + (uint32_t)(((h4 + 0) ^ _e7) << 4), (srcp) + 0);            \
        cp16(_rb + (uint32_t)(((h4 + 1) ^ _e7) << 4), (srcp) + 8);            \
        cp16(_rb + (uint32_t)(((h4 + 2) ^ _e7) << 4), (srcp) + 16);           \
        cp16(_rb + (uint32_t)(((h4 + 3) ^ _e7) << 4), (srcp) + 24);           \
    } while (0)

// =====================================================================
// stage A: act = silu(X@W1^T)*(X@W3^T) — 128 thr, 64x64 warp tiles.
// z==NE1 blocks are riders converting W2/WS2 (scheduled last = drain tail).
// =====================================================================
__global__ __launch_bounds__(128, 2) void ffn_in_mma(
    const float* __restrict__ w2, const float* __restrict__ ws2)
{
    const int e = blockIdx.z;
    if (e == NE1) {
        const size_t total = WBIG + WSML;
        const size_t stride = (size_t)16 * 8 * 128 * 8;
        size_t base = ((size_t)blockIdx.x * 8 + blockIdx.y) * 1024 + (size_t)threadIdx.x * 8;
        for (size_t i = base; i < total; i += stride) {
            if (i < WBIG) cvt8(w2, g_w2h, i);
            else          cvt8(ws2 - WBIG, g_w2h, i);
        }
        return;
    }

    const int cnt = (e == NEXP) ? T_TOK : g_cnt[e];
    const int m0  = blockIdx.x * 128;
    if (m0 >= cnt) return;
    const int n0  = blockIdx.y * 64;

    extern __shared__ char smc[];
    const uint32_t sb = smem_u32(smc);
    const int tid = threadIdx.x;

    const int fr = tid >> 1, h4 = (tid & 1) * 4;
    const int hoff = (tid & 1) * 32;
    int ai0 = m0 + fr;       if (ai0 > cnt - 1) ai0 = cnt - 1;
    int ai1 = m0 + fr + 64;  if (ai1 > cnt - 1) ai1 = cnt - 1;
    const int tok0 = (e == NEXP) ? (m0 + fr)      : g_tok[e][ai0];
    const int tok1 = (e == NEXP) ? (m0 + fr + 64) : g_tok[e][ai1];
    const __half* s0 = g_xrh + (size_t)tok0 * DIM + hoff;
    const __half* s1 = g_xrh + (size_t)tok1 * DIM + hoff;
    const __half* s2 = g_w1h + (size_t)e * INTER * DIM + (size_t)(n0 + fr) * DIM + hoff;
    const __half* s3 = g_w3h + (size_t)e * INTER * DIM + (size_t)(n0 + fr) * DIM + hoff;

    const int lane = tid & 31, warp = tid >> 5;
    const int wm = warp >> 1, wn = warp & 1;
    const int gid = lane >> 2, tig = lane & 3;

    const uint32_t aRowB = (uint32_t)(lane & 15) * 128;
    const uint32_t ahi   = (uint32_t)(lane >> 4) * 16;
    const uint32_t bRowB = ((uint32_t)(lane & 7) + (uint32_t)((lane >> 4) & 1) * 8) * 128;
    const uint32_t bhi   = (uint32_t)((lane >> 3) & 1) * 16;
    const uint32_t sw    = (uint32_t)(lane & 7) * 16;

    float acc1[4][4][4], acc3[4][4][4];
#pragma unroll
    for (int i = 0; i < 4; i++)
#pragma unroll
        for (int j = 0; j < 4; j++)
#pragma unroll
            for (int k = 0; k < 4; k++) { acc1[i][j][k] = 0.f; acc3[i][j][k] = 0.f; }

#define ISSUE_A(kk) do {                                        \
        uint32_t _st = sb + (uint32_t)(((kk) % 3) * STG_BYTES); \
        const int _ko = (kk) * 64;                              \
        FILL_ROW(_st, fr,        s0 + _ko);                     \
        FILL_ROW(_st, fr + 64,   s1 + _ko);                     \
        FILL_ROW(_st, fr + 128,  s2 + _ko);                     \
        FILL_ROW(_st, fr + 192,  s3 + _ko);                     \
        CP_COMMIT();                                            \
    } while (0)

#define LOADF_A(b, ks) do {                                                      \
        const uint32_t _akx = ((uint32_t)((ks) * 32) + ahi) ^ sw;                \
        const uint32_t _bkx = ((uint32_t)((ks) * 32) + bhi) ^ sw;                \
        ldsm4(af[b][0], Ab + 0u * 2048 + _akx);                                  \
        ldsm4(af[b][1], Ab + 1u * 2048 + _akx);                                  \
        ldsm4(af[b][2], Ab + 2u * 2048 + _akx);                                  \
        ldsm4(af[b][3], Ab + 3u * 2048 + _akx);                                  \
        ldsm4(b1f[b][0], B1b + 0u * 2048 + _bkx);                                \
        ldsm4(b1f[b][1], B1b + 1u * 2048 + _bkx);                                \
        ldsm4(b3f[b][0], B3b + 0u * 2048 + _bkx);                                \
        ldsm4(b3f[b][1], B3b + 1u * 2048 + _bkx);                                \
    } while (0)

#define MMA_A(b) do {                                                            \
        _Pragma("unroll")                                                        \
        for (int ntp = 0; ntp < 2; ntp++)                                        \
            _Pragma("unroll")                                                    \
            for (int mt = 0; mt < 4; mt++) {                                     \
                mma_f16(acc1[mt][2 * ntp + 0], af[b][mt], b1f[b][ntp][0], b1f[b][ntp][1]); \
                mma_f16(acc1[mt][2 * ntp + 1], af[b][mt], b1f[b][ntp][2], b1f[b][ntp][3]); \
                mma_f16(acc3[mt][2 * ntp + 0], af[b][mt], b3f[b][ntp][0], b3f[b][ntp][1]); \
                mma_f16(acc3[mt][2 * ntp + 1], af[b][mt], b3f[b][ntp][2], b3f[b][ntp][3]); \
            }                                                                    \
    } while (0)

    ISSUE_A(0);
    ISSUE_A(1);

    uint32_t af[2][4][4], b1f[2][2][4], b3f[2][2][4];

    const int KITER = DIM / 64;
    for (int kk = 0; kk < KITER; kk++) {
        CP_WAIT1();
        __syncthreads();
        if (kk + 2 < KITER) { ISSUE_A(kk + 2); } else { CP_COMMIT(); }

        const uint32_t stage = sb + (uint32_t)((kk % 3) * STG_BYTES);
        const uint32_t Ab  = stage + (uint32_t)(wm * 64) * 128 + aRowB;
        const uint32_t B1b = stage + 16384u + (uint32_t)(wn * 32) * 128 + bRowB;
        const uint32_t B3b = stage + 24576u + (uint32_t)(wn * 32) * 128 + bRowB;

        LOADF_A(0, 0);
#pragma unroll
        for (int ks = 0; ks < 4; ks++) {
            if (ks < 3) LOADF_A((ks + 1) & 1, ks + 1);
            MMA_A(ks & 1);
        }
    }

#pragma unroll
    for (int mt = 0; mt < 4; mt++) {
#pragma unroll
        for (int h = 0; h < 2; h++) {
            const int m = m0 + wm * 64 + mt * 16 + gid + h * 8;
            if (m >= cnt) continue;
            __half* dst = &g_acth[((size_t)e * T_TOK + m) * INTER + n0 + wn * 32];
#pragma unroll
            for (int nt = 0; nt < 4; nt++) {
                float v0 = acc1[mt][nt][h * 2 + 0], u0 = acc3[mt][nt][h * 2 + 0];
                float v1 = acc1[mt][nt][h * 2 + 1], u1 = acc3[mt][nt][h * 2 + 1];
                *(__half2*)(dst + nt * 8 + tig * 2) =
                    __floats2half2_rn((v0 / (1.f + __expf(-v0))) * u0,
                                      (v1 / (1.f + __expf(-v1))) * u1);
            }
        }
    }
#undef ISSUE_A
#undef LOADF_A
#undef MMA_A
}

// =====================================================================
// stage B: y = act @ W2^T — 128 thr, 64x64 warp tiles, frag double-buffered.
// z<NE1: producers (signal g_done). z==NE1: fused-reduce riders
// (spin until all producers done, then out += sum ybuf; reset g_cnt).
// =====================================================================
__global__ __launch_bounds__(128, 2) void ffn_out_mma(float* __restrict__ out)
{
    const int z = blockIdx.z;
    if (z == NE1) {
        // ---- fused reduce rider ----
        if (threadIdx.x == 0) {
            while (*(volatile int*)&g_done < NPROD) { }
        }
        __syncthreads();
        __threadfence();
        const size_t total4 = (size_t)T_TOK * DIM / 4;      // float4 count
        const size_t stride = (size_t)16 * 8 * 128;          // rider threads
        size_t i = ((size_t)blockIdx.x * 8 + blockIdx.y) * 128 + threadIdx.x;
        for (; i < total4; i += stride) {
            size_t idx = i * 4;
            float4 o = *(float4*)(out + idx);
            float4 a = *(const float4*)(&g_ybuf[0][idx]);
            float4 b = *(const float4*)(&g_ybuf[1][idx]);
            float4 c = *(const float4*)(&g_ybuf[2][idx]);
            float4 d = *(const float4*)(&g_ybuf[3][idx]);
            o.x += a.x + b.x + c.x + d.x;
            o.y += a.y + b.y + c.y + d.y;
            o.z += a.z + b.z + c.z + d.z;
            o.w += a.w + b.w + c.w + d.w;
            *(float4*)(out + idx) = o;
        }
        // reset g_cnt for the next replay (all readers finished in earlier kernels)
        if (blockIdx.x == 0 && blockIdx.y == 0 && threadIdx.x < NEXP)
            g_cnt[threadIdx.x] = 0;
        return;
    }

    const int e   = z;
    const int cnt = (e == NEXP) ? T_TOK : g_cnt[e];
    const int m0  = blockIdx.x * 128;
    if (m0 >= cnt) {
        // early-exit producer still signals
        __syncthreads();
        if (threadIdx.x == 0) { __threadfence(); atomicAdd(&g_done, 1); }
        return;
    }
    const int n0  = blockIdx.y * 128;

    extern __shared__ char smc[];
    const uint32_t sb = smem_u32(smc);
    const int tid = threadIdx.x;

    const int fr = tid >> 1, h4 = (tid & 1) * 4;
    const int hoff = (tid & 1) * 32;
    int ai0 = m0 + fr;      if (ai0 > cnt - 1) ai0 = cnt - 1;
    int ai1 = m0 + fr + 64; if (ai1 > cnt - 1) ai1 = cnt - 1;
    const __half* s0 = g_acth + ((size_t)e * T_TOK + ai0) * INTER + hoff;
    const __half* s1 = g_acth + ((size_t)e * T_TOK + ai1) * INTER + hoff;
    const __half* s2 = g_w2h + (size_t)e * DIM * INTER + (size_t)(n0 + fr) * INTER + hoff;
    const __half* s3 = s2 + (size_t)64 * INTER;

    const int lane = tid & 31, warp = tid >> 5;
    const int wm = warp >> 1, wn = warp & 1;
    const int gid = lane >> 2, tig = lane & 3;

    const uint32_t aRowB = (uint32_t)(lane & 15) * 128;
    const uint32_t ahi   = (uint32_t)(lane >> 4) * 16;
    const uint32_t bRowB = ((uint32_t)(lane & 7) + (uint32_t)((lane >> 4) & 1) * 8) * 128;
    const uint32_t bhi   = (uint32_t)((lane >> 3) & 1) * 16;
    const uint32_t sw    = (uint32_t)(lane & 7) * 16;

    float acc[4][8][4];
#pragma unroll
    for (int i = 0; i < 4; i++)
#pragma unroll
        for (int j = 0; j < 8; j++)
#pragma unroll
            for (int k = 0; k < 4; k++) acc[i][j][k] = 0.f;

#define ISSUE_B(kk) do {                                        \
        uint32_t _st = sb + (uint32_t)(((kk) % 3) * STG_BYTES); \
        const int _ko = (kk) * 64;                              \
        FILL_ROW(_st, fr,        s0 + _ko);                     \
        FILL_ROW(_st, fr + 64,   s1 + _ko);                     \
        FILL_ROW(_st, fr + 128,  s2 + _ko);                     \
        FILL_ROW(_st, fr + 192,  s3 + _ko);                     \
        CP_COMMIT();                                            \
    } while (0)

#define LOADF_B(b, ks) do {                                                      \
        const uint32_t _akx = ((uint32_t)((ks) * 32) + ahi) ^ sw;                \
        const uint32_t _bkx = ((uint32_t)((ks) * 32) + bhi) ^ sw;                \
        ldsm4(af[b][0], Ab + 0u * 2048 + _akx);                                  \
        ldsm4(af[b][1], Ab + 1u * 2048 + _akx);                                  \
        ldsm4(af[b][2], Ab + 2u * 2048 + _akx);                                  \
        ldsm4(af[b][3], Ab + 3u * 2048 + _akx);                                  \
        ldsm4(bf[b][0], Bb + 0u * 2048 + _bkx);                                  \
        ldsm4(bf[b][1], Bb + 1u * 2048 + _bkx);                                  \
        ldsm4(bf[b][2], Bb + 2u * 2048 + _bkx);                                  \
        ldsm4(bf[b][3], Bb + 3u * 2048 + _bkx);                                  \
    } while (0)

#define MMA_B(b) do {                                                            \
        _Pragma("unroll")                                                        \
        for (int ntp = 0; ntp < 4; ntp++)                                        \
            _Pragma("unroll")                                                    \
            for (int mt = 0; mt < 4; mt++) {                                     \
                mma_f16(acc[mt][2 * ntp + 0], af[b][mt], bf[b][ntp][0], bf[b][ntp][1]); \
                mma_f16(acc[mt][2 * ntp + 1], af[b][mt], bf[b][ntp][2], bf[b][ntp][3]); \
            }                                                                    \
    } while (0)

    ISSUE_B(0);
    ISSUE_B(1);

    uint32_t af[2][4][4], bf[2][4][4];

    const int KITER = INTER / 64;
    for (int kk = 0; kk < KITER; kk++) {
        CP_WAIT1();
        __syncthreads();
        if (kk + 2 < KITER) { ISSUE_B(kk + 2); } else { CP_COMMIT(); }

        const uint32_t stage = sb + (uint32_t)((kk % 3) * STG_BYTES);
        const uint32_t Ab = stage + (uint32_t)(wm * 64) * 128 + aRowB;
        const uint32_t Bb = stage + 16384u + (uint32_t)(wn * 64) * 128 + bRowB;

        LOADF_B(0, 0);
#pragma unroll
        for (int ks = 0; ks < 4; ks++) {
            if (ks < 3) LOADF_B((ks + 1) & 1, ks + 1);
            MMA_B(ks & 1);
        }
    }

    // epilogue: shared expert -> out; routed -> ybuf[slot]
#pragma unroll
    for (int mt = 0; mt < 4; mt++) {
#pragma unroll
        for (int h = 0; h < 2; h++) {
            const int m = m0 + wm * 64 + mt * 16 + gid + h * 8;
            if (m >= cnt) continue;
            float wt = 1.f;
            float* dst;
            if (e == NEXP) {
                dst = out + (size_t)m * DIM + n0 + wn * 64;
            } else {
                const int tokm = g_tok[e][m];
                const int sl   = g_slot[e][m];
                wt             = g_wt[e][m];
                dst = &g_ybuf[sl][(size_t)tokm * DIM + n0 + wn * 64];
            }
#pragma unroll
            for (int nt = 0; nt < 8; nt++) {
                *(float2*)(dst + nt * 8 + tig * 2) =
                    make_float2(acc[mt][nt][h * 2 + 0] * wt,
                                acc[mt][nt][h * 2 + 1] * wt);
            }
        }
    }

    // signal completion
    __syncthreads();
    if (tid == 0) { __threadfence(); atomicAdd(&g_done, 1); }
#undef ISSUE_B
#undef LOADF_B
#undef MMA_B
}

// ---------------- launch ----------------
extern "C" void kernel_launch(void* const* d_in, const int* in_sizes, int n_in,
                              void* d_out, int out_size) {
    const float* x   = (const float*)d_in[0];
    const float* gw  = (const float*)d_in[1];
    const float* gb  = (const float*)d_in[2];
    const float* w1  = (const float*)d_in[3];
    const float* w2  = (const float*)d_in[4];
    const float* w3  = (const float*)d_in[5];
    const float* ws1 = (const float*)d_in[6];
    const float* ws2 = (const float*)d_in[7];
    const float* ws3 = (const float*)d_in[8];
    float* out = (float*)d_out;

    cudaFuncSetAttribute(ffn_in_mma,  cudaFuncAttributeMaxDynamicSharedMemorySize, SMEM_BYTES);
    cudaFuncSetAttribute(ffn_out_mma, cudaFuncAttributeMaxDynamicSharedMemorySize, SMEM_BYTES);

    prep_kernel<<<8960, 256>>>(x, gw, gb, w1, w3, ws1, ws3);
    ffn_in_mma<<<dim3(T_TOK / 128, INTER / 64, NE1 + 1), 128, SMEM_BYTES>>>(w2, ws2);
    ffn_out_mma<<<dim3(T_TOK / 128, DIM / 128, NE1 + 1), 128, SMEM_BYTES>>>(out);
}

// round 16
// speedup vs baseline: 1.0910x; 1.0910x over previous
#include <cuda_runtime.h>
#include <cuda_fp16.h>
#include <math.h>
#include <stdint.h>

#define T_TOK 2048
#define DIM   1024
#define INTER 512
#define NEXP  16
#define TOPK  4
#define NGRP  4
#define GSZ   4
#define NE1   (NEXP + 1)

#define STG_BYTES 32768
#define SMEM_BYTES (3 * STG_BYTES)

#define WBIG  ((size_t)NEXP * INTER * DIM)
#define WSML  ((size_t)INTER * DIM)

// ---------------- scratch ----------------
__device__ int           g_cnt[NEXP];
__device__ int           g_tok[NEXP][T_TOK];
__device__ unsigned char g_slot[NEXP][T_TOK];
__device__ float         g_wt[NEXP][T_TOK];
__device__ __half        g_xrh[(size_t)T_TOK * DIM];
__device__ __half        g_acth[(size_t)NE1 * T_TOK * INTER];
__device__ float         g_ybuf[TOPK][(size_t)T_TOK * DIM];
__device__ __half        g_w1h[WBIG + WSML];
__device__ __half        g_w3h[WBIG + WSML];
__device__ __half        g_w2h[WBIG + WSML];

// ---------------- helpers ----------------
__device__ __forceinline__ uint32_t smem_u32(const void* p) {
    uint32_t a;
    asm("{ .reg .u64 t; cvta.to.shared.u64 t, %1; cvt.u32.u64 %0, t; }" : "=r"(a) : "l"(p));
    return a;
}
__device__ __forceinline__ void cp16(uint32_t dst, const void* src) {
    asm volatile("cp.async.cg.shared.global [%0], [%1], 16;" :: "r"(dst), "l"(src));
}
#define CP_COMMIT() asm volatile("cp.async.commit_group;")
#define CP_WAIT1()  asm volatile("cp.async.wait_group 1;")

__device__ __forceinline__ void ldsm4(uint32_t* r, uint32_t addr) {
    asm volatile("ldmatrix.sync.aligned.m8n8.x4.shared.b16 {%0,%1,%2,%3}, [%4];"
                 : "=r"(r[0]), "=r"(r[1]), "=r"(r[2]), "=r"(r[3]) : "r"(addr));
}
__device__ __forceinline__ void mma_f16(float* d, const uint32_t* a, uint32_t b0, uint32_t b1) {
    asm volatile(
        "mma.sync.aligned.m16n8k16.row.col.f32.f16.f16.f32 "
        "{%0,%1,%2,%3}, {%4,%5,%6,%7}, {%8,%9}, {%0,%1,%2,%3};"
        : "+f"(d[0]), "+f"(d[1]), "+f"(d[2]), "+f"(d[3])
        : "r"(a[0]), "r"(a[1]), "r"(a[2]), "r"(a[3]), "r"(b0), "r"(b1));
}

// convert 8 fp32 -> 8 fp16 (vectorized)
__device__ __forceinline__ void cvt8(const float* src, __half* dst, size_t i) {
    float4 a = *(const float4*)(src + i);
    float4 b = *(const float4*)(src + i + 4);
    __half2 h0 = __floats2half2_rn(a.x, a.y), h1 = __floats2half2_rn(a.z, a.w);
    __half2 h2 = __floats2half2_rn(b.x, b.y), h3 = __floats2half2_rn(b.z, b.w);
    uint4 o;
    o.x = *(uint32_t*)&h0; o.y = *(uint32_t*)&h1;
    o.z = *(uint32_t*)&h2; o.w = *(uint32_t*)&h3;
    *(uint4*)(dst + i) = o;
}

// convert 32 elements with 4 independent LDG.128 in flight (MLP=4)
__device__ __forceinline__ void cvt32_mlp4(const float* src, __half* dst, size_t base) {
    float4 a0 = *(const float4*)(src + base);
    float4 b0 = *(const float4*)(src + base + 4);
    float4 a1 = *(const float4*)(src + base + 2048);
    float4 b1 = *(const float4*)(src + base + 2052);
    float4 a2 = *(const float4*)(src + base + 4096);
    float4 b2 = *(const float4*)(src + base + 4100);
    float4 a3 = *(const float4*)(src + base + 6144);
    float4 b3 = *(const float4*)(src + base + 6148);
#define PACK8(A, B, OFF) do {                                                   \
        __half2 h0 = __floats2half2_rn((A).x, (A).y);                           \
        __half2 h1 = __floats2half2_rn((A).z, (A).w);                           \
        __half2 h2 = __floats2half2_rn((B).x, (B).y);                           \
        __half2 h3 = __floats2half2_rn((B).z, (B).w);                           \
        uint4 o;                                                                \
        o.x = *(uint32_t*)&h0; o.y = *(uint32_t*)&h1;                           \
        o.z = *(uint32_t*)&h2; o.w = *(uint32_t*)&h3;                           \
        *(uint4*)(dst + base + (OFF)) = o;                                      \
    } while (0)
    PACK8(a0, b0, 0);
    PACK8(a1, b1, 2048);
    PACK8(a2, b2, 4096);
    PACK8(a3, b3, 6144);
#undef PACK8
}

// ---------------- init ----------------
__global__ void init_kernel() {
    if (threadIdx.x < NEXP) g_cnt[threadIdx.x] = 0;
}

// ---------------- prep: gate (blocks 0-255) + convert w1/w3/ws1/ws3 (MLP=4) ----------------
__global__ __launch_bounds__(256) void prep_kernel(
    const float* __restrict__ x, const float* __restrict__ gw,
    const float* __restrict__ gbias,
    const float* __restrict__ w1, const float* __restrict__ w3,
    const float* __restrict__ ws1, const float* __restrict__ ws3)
{
    const int bid = blockIdx.x;
    if (bid >= 256) {
        // conversion: each block handles 8192 elements (256 thr x 32 elems, MLP=4)
        int idx = bid - 256;
        const float* src; __half* dst;
        if (idx < 1024)      { src = w1;  dst = g_w1h; }
        else if (idx < 2048) { src = w3;  dst = g_w3h;        idx -= 1024; }
        else if (idx < 2112) { src = ws1; dst = g_w1h + WBIG; idx -= 2048; }
        else                 { src = ws3; dst = g_w3h + WBIG; idx -= 2112; }
        size_t base = (size_t)idx * 8192 + (size_t)threadIdx.x * 8;
        cvt32_mlp4(src, dst, base);
        return;
    }

    // ---- gate: 1 warp per token ----
    int t    = bid * 8 + (threadIdx.x >> 5);
    int lane = threadIdx.x & 31;

    float4 xr[8];
    const float4* xp = (const float4*)(x + (size_t)t * DIM) + lane;
#pragma unroll
    for (int i = 0; i < 8; i++) xr[i] = xp[i * 32];

    __half* xo = g_xrh + (size_t)t * DIM + lane * 4;
#pragma unroll
    for (int i = 0; i < 8; i++) {
        __half2 lo = __floats2half2_rn(xr[i].x, xr[i].y);
        __half2 hi = __floats2half2_rn(xr[i].z, xr[i].w);
        uint2 u;
        u.x = *(uint32_t*)&lo; u.y = *(uint32_t*)&hi;
        *(uint2*)(xo + i * 128) = u;
    }

    float sc[NEXP];
#pragma unroll
    for (int e = 0; e < NEXP; e++) {
        const float4* w = (const float4*)(gw + (size_t)e * DIM) + lane;
        float acc = 0.f;
#pragma unroll
        for (int i = 0; i < 8; i++) {
            float4 wv = w[i * 32];
            acc += xr[i].x * wv.x + xr[i].y * wv.y + xr[i].z * wv.z + xr[i].w * wv.w;
        }
#pragma unroll
        for (int o = 16; o > 0; o >>= 1) acc += __shfl_xor_sync(0xffffffffu, acc, o);
        sc[e] = 1.f / (1.f + __expf(-acc));
    }
    if (lane == 0) {
        float s[NEXP];
#pragma unroll
        for (int e = 0; e < NEXP; e++) s[e] = sc[e] + gbias[e];
        float gm[NGRP];
#pragma unroll
        for (int g = 0; g < NGRP; g++) {
            float m = s[g * GSZ];
#pragma unroll
            for (int j = 1; j < GSZ; j++) m = fmaxf(m, s[g * GSZ + j]);
            gm[g] = m;
        }
        int g1 = 0;
#pragma unroll
        for (int g = 1; g < NGRP; g++) if (gm[g] > gm[g1]) g1 = g;
        int g2 = -1;
#pragma unroll
        for (int g = 0; g < NGRP; g++) {
            if (g == g1) continue;
            if (g2 < 0 || gm[g] > gm[g2]) g2 = g;
        }
        float sm[NEXP];
#pragma unroll
        for (int e = 0; e < NEXP; e++) {
            int g = e / GSZ;
            sm[e] = (g == g1 || g == g2) ? s[e] : -1e30f;
        }
#pragma unroll
        for (int k = 0; k < TOPK; k++) {
            int best = 0; float bv = -1e38f;
#pragma unroll
            for (int e = 0; e < NEXP; e++) if (sm[e] > bv) { bv = sm[e]; best = e; }
            sm[best] = -1e38f;
            int pos = atomicAdd(&g_cnt[best], 1);
            g_tok[best][pos]  = t;
            g_slot[best][pos] = (unsigned char)k;
            g_wt[best][pos]   = sc[best];
        }
    }
}

#define FILL_ROW(stageu, R, srcp) do {                                        \
        uint32_t _rb = (stageu) + (uint32_t)(R) * 128;                        \
        int _e7 = (R) & 7;                                                    \
        cp16(_rb + (uint32_t)(((h4 + 0) ^ _e7) << 4), (srcp) + 0);            \
        cp16(_rb + (uint32_t)(((h4 + 1) ^ _e7) << 4), (srcp) + 8);            \
        cp16(_rb + (uint32_t)(((h4 + 2) ^ _e7) << 4), (srcp) + 16);           \
        cp16(_rb + (uint32_t)(((h4 + 3) ^ _e7) << 4), (srcp) + 24);           \
    } while (0)

// =====================================================================
// stage A: act = silu(X@W1^T)*(X@W3^T) — 128 thr, 64x64 warp tiles.
// z==NE1 blocks are riders converting W2/WS2 (scheduled last = drain tail).
// =====================================================================
__global__ __launch_bounds__(128, 2) void ffn_in_mma(
    const float* __restrict__ w2, const float* __restrict__ ws2)
{
    const int e = blockIdx.z;
    if (e == NE1) {
        const size_t total = WBIG + WSML;
        const size_t stride = (size_t)16 * 8 * 128 * 8;
        size_t base = ((size_t)blockIdx.x * 8 + blockIdx.y) * 1024 + (size_t)threadIdx.x * 8;
        for (size_t i = base; i < total; i += stride) {
            if (i < WBIG) cvt8(w2, g_w2h, i);
            else          cvt8(ws2 - WBIG, g_w2h, i);
        }
        return;
    }

    const int cnt = (e == NEXP) ? T_TOK : g_cnt[e];
    const int m0  = blockIdx.x * 128;
    if (m0 >= cnt) return;
    const int n0  = blockIdx.y * 64;

    extern __shared__ char smc[];
    const uint32_t sb = smem_u32(smc);
    const int tid = threadIdx.x;

    const int fr = tid >> 1, h4 = (tid & 1) * 4;
    const int hoff = (tid & 1) * 32;
    int ai0 = m0 + fr;       if (ai0 > cnt - 1) ai0 = cnt - 1;
    int ai1 = m0 + fr + 64;  if (ai1 > cnt - 1) ai1 = cnt - 1;
    const int tok0 = (e == NEXP) ? (m0 + fr)      : g_tok[e][ai0];
    const int tok1 = (e == NEXP) ? (m0 + fr + 64) : g_tok[e][ai1];
    const __half* s0 = g_xrh + (size_t)tok0 * DIM + hoff;
    const __half* s1 = g_xrh + (size_t)tok1 * DIM + hoff;
    const __half* s2 = g_w1h + (size_t)e * INTER * DIM + (size_t)(n0 + fr) * DIM + hoff;
    const __half* s3 = g_w3h + (size_t)e * INTER * DIM + (size_t)(n0 + fr) * DIM + hoff;

    const int lane = tid & 31, warp = tid >> 5;
    const int wm = warp >> 1, wn = warp & 1;
    const int gid = lane >> 2, tig = lane & 3;

    const uint32_t aRowB = (uint32_t)(lane & 15) * 128;
    const uint32_t ahi   = (uint32_t)(lane >> 4) * 16;
    const uint32_t bRowB = ((uint32_t)(lane & 7) + (uint32_t)((lane >> 4) & 1) * 8) * 128;
    const uint32_t bhi   = (uint32_t)((lane >> 3) & 1) * 16;
    const uint32_t sw    = (uint32_t)(lane & 7) * 16;

    float acc1[4][4][4], acc3[4][4][4];
#pragma unroll
    for (int i = 0; i < 4; i++)
#pragma unroll
        for (int j = 0; j < 4; j++)
#pragma unroll
            for (int k = 0; k < 4; k++) { acc1[i][j][k] = 0.f; acc3[i][j][k] = 0.f; }

#define ISSUE_A(kk) do {                                        \
        uint32_t _st = sb + (uint32_t)(((kk) % 3) * STG_BYTES); \
        const int _ko = (kk) * 64;                              \
        FILL_ROW(_st, fr,        s0 + _ko);                     \
        FILL_ROW(_st, fr + 64,   s1 + _ko);                     \
        FILL_ROW(_st, fr + 128,  s2 + _ko);                     \
        FILL_ROW(_st, fr + 192,  s3 + _ko);                     \
        CP_COMMIT();                                            \
    } while (0)

#define LOADF_A(b, ks) do {                                                      \
        const uint32_t _akx = ((uint32_t)((ks) * 32) + ahi) ^ sw;                \
        const uint32_t _bkx = ((uint32_t)((ks) * 32) + bhi) ^ sw;                \
        ldsm4(af[b][0], Ab + 0u * 2048 + _akx);                                  \
        ldsm4(af[b][1], Ab + 1u * 2048 + _akx);                                  \
        ldsm4(af[b][2], Ab + 2u * 2048 + _akx);                                  \
        ldsm4(af[b][3], Ab + 3u * 2048 + _akx);                                  \
        ldsm4(b1f[b][0], B1b + 0u * 2048 + _bkx);                                \
        ldsm4(b1f[b][1], B1b + 1u * 2048 + _bkx);                                \
        ldsm4(b3f[b][0], B3b + 0u * 2048 + _bkx);                                \
        ldsm4(b3f[b][1], B3b + 1u * 2048 + _bkx);                                \
    } while (0)

#define MMA_A(b) do {                                                            \
        _Pragma("unroll")                                                        \
        for (int ntp = 0; ntp < 2; ntp++)                                        \
            _Pragma("unroll")                                                    \
            for (int mt = 0; mt < 4; mt++) {                                     \
                mma_f16(acc1[mt][2 * ntp + 0], af[b][mt], b1f[b][ntp][0], b1f[b][ntp][1]); \
                mma_f16(acc1[mt][2 * ntp + 1], af[b][mt], b1f[b][ntp][2], b1f[b][ntp][3]); \
                mma_f16(acc3[mt][2 * ntp + 0], af[b][mt], b3f[b][ntp][0], b3f[b][ntp][1]); \
                mma_f16(acc3[mt][2 * ntp + 1], af[b][mt], b3f[b][ntp][2], b3f[b][ntp][3]); \
            }                                                                    \
    } while (0)

    ISSUE_A(0);
    ISSUE_A(1);

    uint32_t af[2][4][4], b1f[2][2][4], b3f[2][2][4];

    const int KITER = DIM / 64;
    for (int kk = 0; kk < KITER; kk++) {
        CP_WAIT1();
        __syncthreads();
        if (kk + 2 < KITER) { ISSUE_A(kk + 2); } else { CP_COMMIT(); }

        const uint32_t stage = sb + (uint32_t)((kk % 3) * STG_BYTES);
        const uint32_t Ab  = stage + (uint32_t)(wm * 64) * 128 + aRowB;
        const uint32_t B1b = stage + 16384u + (uint32_t)(wn * 32) * 128 + bRowB;
        const uint32_t B3b = stage + 24576u + (uint32_t)(wn * 32) * 128 + bRowB;

        LOADF_A(0, 0);
#pragma unroll
        for (int ks = 0; ks < 4; ks++) {
            if (ks < 3) LOADF_A((ks + 1) & 1, ks + 1);
            MMA_A(ks & 1);
        }
    }

#pragma unroll
    for (int mt = 0; mt < 4; mt++) {
#pragma unroll
        for (int h = 0; h < 2; h++) {
            const int m = m0 + wm * 64 + mt * 16 + gid + h * 8;
            if (m >= cnt) continue;
            __half* dst = &g_acth[((size_t)e * T_TOK + m) * INTER + n0 + wn * 32];
#pragma unroll
            for (int nt = 0; nt < 4; nt++) {
                float v0 = acc1[mt][nt][h * 2 + 0], u0 = acc3[mt][nt][h * 2 + 0];
                float v1 = acc1[mt][nt][h * 2 + 1], u1 = acc3[mt][nt][h * 2 + 1];
                *(__half2*)(dst + nt * 8 + tig * 2) =
                    __floats2half2_rn((v0 / (1.f + __expf(-v0))) * u0,
                                      (v1 / (1.f + __expf(-v1))) * u1);
            }
        }
    }
#undef ISSUE_A
#undef LOADF_A
#undef MMA_A
}

// =====================================================================
// stage B: y = act @ W2^T — 128 thr, 64x64 warp tiles, frag double-buffered
// =====================================================================
__global__ __launch_bounds__(128, 2) void ffn_out_mma(float* __restrict__ out)
{
    const int e   = blockIdx.z;
    const int cnt = (e == NEXP) ? T_TOK : g_cnt[e];
    const int m0  = blockIdx.x * 128;
    if (m0 >= cnt) return;
    const int n0  = blockIdx.y * 128;

    extern __shared__ char smc[];
    const uint32_t sb = smem_u32(smc);
    const int tid = threadIdx.x;

    const int fr = tid >> 1, h4 = (tid & 1) * 4;
    const int hoff = (tid & 1) * 32;
    int ai0 = m0 + fr;      if (ai0 > cnt - 1) ai0 = cnt - 1;
    int ai1 = m0 + fr + 64; if (ai1 > cnt - 1) ai1 = cnt - 1;
    const __half* s0 = g_acth + ((size_t)e * T_TOK + ai0) * INTER + hoff;
    const __half* s1 = g_acth + ((size_t)e * T_TOK + ai1) * INTER + hoff;
    const __half* s2 = g_w2h + (size_t)e * DIM * INTER + (size_t)(n0 + fr) * INTER + hoff;
    const __half* s3 = s2 + (size_t)64 * INTER;

    const int lane = tid & 31, warp = tid >> 5;
    const int wm = warp >> 1, wn = warp & 1;
    const int gid = lane >> 2, tig = lane & 3;

    const uint32_t aRowB = (uint32_t)(lane & 15) * 128;
    const uint32_t ahi   = (uint32_t)(lane >> 4) * 16;
    const uint32_t bRowB = ((uint32_t)(lane & 7) + (uint32_t)((lane >> 4) & 1) * 8) * 128;
    const uint32_t bhi   = (uint32_t)((lane >> 3) & 1) * 16;
    const uint32_t sw    = (uint32_t)(lane & 7) * 16;

    float acc[4][8][4];
#pragma unroll
    for (int i = 0; i < 4; i++)
#pragma unroll
        for (int j = 0; j < 8; j++)
#pragma unroll
            for (int k = 0; k < 4; k++) acc[i][j][k] = 0.f;

#define ISSUE_B(kk) do {                                        \
        uint32_t _st = sb + (uint32_t)(((kk) % 3) * STG_BYTES); \
        const int _ko = (kk) * 64;                              \
        FILL_ROW(_st, fr,        s0 + _ko);                     \
        FILL_ROW(_st, fr + 64,   s1 + _ko);                     \
        FILL_ROW(_st, fr + 128,  s2 + _ko);                     \
        FILL_ROW(_st, fr + 192,  s3 + _ko);                     \
        CP_COMMIT();                                            \
    } while (0)

#define LOADF_B(b, ks) do {                                                      \
        const uint32_t _akx = ((uint32_t)((ks) * 32) + ahi) ^ sw;                \
        const uint32_t _bkx = ((uint32_t)((ks) * 32) + bhi) ^ sw;                \
        ldsm4(af[b][0], Ab + 0u * 2048 + _akx);                                  \
        ldsm4(af[b][1], Ab + 1u * 2048 + _akx);                                  \
        ldsm4(af[b][2], Ab + 2u * 2048 + _akx);                                  \
        ldsm4(af[b][3], Ab + 3u * 2048 + _akx);                                  \
        ldsm4(bf[b][0], Bb + 0u * 2048 + _bkx);                                  \
        ldsm4(bf[b][1], Bb + 1u * 2048 + _bkx);                                  \
        ldsm4(bf[b][2], Bb + 2u * 2048 + _bkx);                                  \
        ldsm4(bf[b][3], Bb + 3u * 2048 + _bkx);                                  \
    } while (0)

#define MMA_B(b) do {                                                            \
        _Pragma("unroll")                                                        \
        for (int ntp = 0; ntp < 4; ntp++)                                        \
            _Pragma("unroll")                                                    \
            for (int mt = 0; mt < 4; mt++) {                                     \
                mma_f16(acc[mt][2 * ntp + 0], af[b][mt], bf[b][ntp][0], bf[b][ntp][1]); \
                mma_f16(acc[mt][2 * ntp + 1], af[b][mt], bf[b][ntp][2], bf[b][ntp][3]); \
            }                                                                    \
    } while (0)

    ISSUE_B(0);
    ISSUE_B(1);

    uint32_t af[2][4][4], bf[2][4][4];

    const int KITER = INTER / 64;
    for (int kk = 0; kk < KITER; kk++) {
        CP_WAIT1();
        __syncthreads();
        if (kk + 2 < KITER) { ISSUE_B(kk + 2); } else { CP_COMMIT(); }

        const uint32_t stage = sb + (uint32_t)((kk % 3) * STG_BYTES);
        const uint32_t Ab = stage + (uint32_t)(wm * 64) * 128 + aRowB;
        const uint32_t Bb = stage + 16384u + (uint32_t)(wn * 64) * 128 + bRowB;

        LOADF_B(0, 0);
#pragma unroll
        for (int ks = 0; ks < 4; ks++) {
            if (ks < 3) LOADF_B((ks + 1) & 1, ks + 1);
            MMA_B(ks & 1);
        }
    }

#pragma unroll
    for (int mt = 0; mt < 4; mt++) {
#pragma unroll
        for (int h = 0; h < 2; h++) {
            const int m = m0 + wm * 64 + mt * 16 + gid + h * 8;
            if (m >= cnt) continue;
            float wt = 1.f;
            float* dst;
            if (e == NEXP) {
                dst = out + (size_t)m * DIM + n0 + wn * 64;
            } else {
                const int tokm = g_tok[e][m];
                const int sl   = g_slot[e][m];
                wt             = g_wt[e][m];
                dst = &g_ybuf[sl][(size_t)tokm * DIM + n0 + wn * 64];
            }
#pragma unroll
            for (int nt = 0; nt < 8; nt++) {
                *(float2*)(dst + nt * 8 + tig * 2) =
                    make_float2(acc[mt][nt][h * 2 + 0] * wt,
                                acc[mt][nt][h * 2 + 1] * wt);
            }
        }
    }
#undef ISSUE_B
#undef LOADF_B
#undef MMA_B
}

// ---------------- reduce ----------------
__global__ void reduce_kernel(float* __restrict__ out) {
    size_t idx = ((size_t)blockIdx.x * blockDim.x + threadIdx.x) * 4;
    if (idx < (size_t)T_TOK * DIM) {
        float4 o = *(float4*)(out + idx);
        float4 a = *(const float4*)(&g_ybuf[0][idx]);
        float4 b = *(const float4*)(&g_ybuf[1][idx]);
        float4 c = *(const float4*)(&g_ybuf[2][idx]);
        float4 d = *(const float4*)(&g_ybuf[3][idx]);
        o.x += a.x + b.x + c.x + d.x;
        o.y += a.y + b.y + c.y + d.y;
        o.z += a.z + b.z + c.z + d.z;
        o.w += a.w + b.w + c.w + d.w;
        *(float4*)(out + idx) = o;
    }
}

// ---------------- launch ----------------
extern "C" void kernel_launch(void* const* d_in, const int* in_sizes, int n_in,
                              void* d_out, int out_size) {
    const float* x   = (const float*)d_in[0];
    const float* gw  = (const float*)d_in[1];
    const float* gb  = (const float*)d_in[2];
    const float* w1  = (const float*)d_in[3];
    const float* w2  = (const float*)d_in[4];
    const float* w3  = (const float*)d_in[5];
    const float* ws1 = (const float*)d_in[6];
    const float* ws2 = (const float*)d_in[7];
    const float* ws3 = (const float*)d_in[8];
    float* out = (float*)d_out;

    cudaFuncSetAttribute(ffn_in_mma,  cudaFuncAttributeMaxDynamicSharedMemorySize, SMEM_BYTES);
    cudaFuncSetAttribute(ffn_out_mma, cudaFuncAttributeMaxDynamicSharedMemorySize, SMEM_BYTES);

    init_kernel<<<1, 32>>>();
    // gate (256 blocks) + convert w1/w3/ws1/ws3 (2176 blocks, MLP=4)
    prep_kernel<<<2432, 256>>>(x, gw, gb, w1, w3, ws1, ws3);
    ffn_in_mma<<<dim3(T_TOK / 128, INTER / 64, NE1 + 1), 128, SMEM_BYTES>>>(w2, ws2);
    ffn_out_mma<<<dim3(T_TOK / 128, DIM / 128, NE1), 128, SMEM_BYTES>>>(out);
    reduce_kernel<<<(T_TOK * DIM / 4 + 255) / 256, 256>>>(out);
}

// round 17
// speedup vs baseline: 1.1298x; 1.0356x over previous
#include <cuda_runtime.h>
#include <cuda_fp16.h>
#include <math.h>
#include <stdint.h>

#define T_TOK 2048
#define DIM   1024
#define INTER 512
#define NEXP  16
#define TOPK  4
#define NGRP  4
#define GSZ   4
#define NE1   (NEXP + 1)

#define STG_BYTES 32768
#define SMEM_BYTES (3 * STG_BYTES)

#define WBIG  ((size_t)NEXP * INTER * DIM)
#define WSML  ((size_t)INTER * DIM)

// ---------------- scratch ----------------
__device__ int           g_cnt[NEXP];   // zero at start (.bss); re-zeroed by reduce each call
__device__ int           g_tok[NEXP][T_TOK];
__device__ unsigned char g_slot[NEXP][T_TOK];
__device__ float         g_wt[NEXP][T_TOK];
__device__ __half        g_xrh[(size_t)T_TOK * DIM];
__device__ __half        g_acth[(size_t)NE1 * T_TOK * INTER];
__device__ float         g_ybuf[TOPK][(size_t)T_TOK * DIM];
__device__ __half        g_w1h[WBIG + WSML];
__device__ __half        g_w3h[WBIG + WSML];
__device__ __half        g_w2h[WBIG + WSML];

// ---------------- helpers ----------------
__device__ __forceinline__ uint32_t smem_u32(const void* p) {
    uint32_t a;
    asm("{ .reg .u64 t; cvta.to.shared.u64 t, %1; cvt.u32.u64 %0, t; }" : "=r"(a) : "l"(p));
    return a;
}
__device__ __forceinline__ void cp16(uint32_t dst, const void* src) {
    asm volatile("cp.async.cg.shared.global [%0], [%1], 16;" :: "r"(dst), "l"(src));
}
#define CP_COMMIT() asm volatile("cp.async.commit_group;")
#define CP_WAIT1()  asm volatile("cp.async.wait_group 1;")

__device__ __forceinline__ void ldsm4(uint32_t* r, uint32_t addr) {
    asm volatile("ldmatrix.sync.aligned.m8n8.x4.shared.b16 {%0,%1,%2,%3}, [%4];"
                 : "=r"(r[0]), "=r"(r[1]), "=r"(r[2]), "=r"(r[3]) : "r"(addr));
}
__device__ __forceinline__ void mma_f16(float* d, const uint32_t* a, uint32_t b0, uint32_t b1) {
    asm volatile(
        "mma.sync.aligned.m16n8k16.row.col.f32.f16.f16.f32 "
        "{%0,%1,%2,%3}, {%4,%5,%6,%7}, {%8,%9}, {%0,%1,%2,%3};"
        : "+f"(d[0]), "+f"(d[1]), "+f"(d[2]), "+f"(d[3])
        : "r"(a[0]), "r"(a[1]), "r"(a[2]), "r"(a[3]), "r"(b0), "r"(b1));
}

// convert 8 fp32 -> 8 fp16 (vectorized)
__device__ __forceinline__ void cvt8(const float* src, __half* dst, size_t i) {
    float4 a = *(const float4*)(src + i);
    float4 b = *(const float4*)(src + i + 4);
    __half2 h0 = __floats2half2_rn(a.x, a.y), h1 = __floats2half2_rn(a.z, a.w);
    __half2 h2 = __floats2half2_rn(b.x, b.y), h3 = __floats2half2_rn(b.z, b.w);
    uint4 o;
    o.x = *(uint32_t*)&h0; o.y = *(uint32_t*)&h1;
    o.z = *(uint32_t*)&h2; o.w = *(uint32_t*)&h3;
    *(uint4*)(dst + i) = o;
}

// convert 64 elements with 8 independent LDG.128 in flight (MLP=8)
__device__ __forceinline__ void cvt64_mlp8(const float* src, __half* dst, size_t base) {
    float4 a[8], b[8];
#pragma unroll
    for (int q = 0; q < 8; q++) {
        a[q] = *(const float4*)(src + base + (size_t)q * 2048);
        b[q] = *(const float4*)(src + base + (size_t)q * 2048 + 4);
    }
#pragma unroll
    for (int q = 0; q < 8; q++) {
        __half2 h0 = __floats2half2_rn(a[q].x, a[q].y);
        __half2 h1 = __floats2half2_rn(a[q].z, a[q].w);
        __half2 h2 = __floats2half2_rn(b[q].x, b[q].y);
        __half2 h3 = __floats2half2_rn(b[q].z, b[q].w);
        uint4 o;
        o.x = *(uint32_t*)&h0; o.y = *(uint32_t*)&h1;
        o.z = *(uint32_t*)&h2; o.w = *(uint32_t*)&h3;
        *(uint4*)(dst + base + (size_t)q * 2048) = o;
    }
}

// ---------------- prep: gate (blocks 0-255) + convert w1/w3/ws1/ws3 (MLP=8) ----------------
__global__ __launch_bounds__(256) void prep_kernel(
    const float* __restrict__ x, const float* __restrict__ gw,
    const float* __restrict__ gbias,
    const float* __restrict__ w1, const float* __restrict__ w3,
    const float* __restrict__ ws1, const float* __restrict__ ws3)
{
    const int bid = blockIdx.x;
    if (bid >= 256) {
        // conversion: each block handles 16384 elements (256 thr x 64 elems, MLP=8)
        int idx = bid - 256;
        const float* src; __half* dst;
        if (idx < 512)       { src = w1;  dst = g_w1h; }
        else if (idx < 1024) { src = w3;  dst = g_w3h;        idx -= 512; }
        else if (idx < 1056) { src = ws1; dst = g_w1h + WBIG; idx -= 1024; }
        else                 { src = ws3; dst = g_w3h + WBIG; idx -= 1056; }
        size_t base = (size_t)idx * 16384 + (size_t)threadIdx.x * 8;
        cvt64_mlp8(src, dst, base);
        return;
    }

    // ---- gate: 1 warp per token ----
    int t    = bid * 8 + (threadIdx.x >> 5);
    int lane = threadIdx.x & 31;

    float4 xr[8];
    const float4* xp = (const float4*)(x + (size_t)t * DIM) + lane;
#pragma unroll
    for (int i = 0; i < 8; i++) xr[i] = xp[i * 32];

    __half* xo = g_xrh + (size_t)t * DIM + lane * 4;
#pragma unroll
    for (int i = 0; i < 8; i++) {
        __half2 lo = __floats2half2_rn(xr[i].x, xr[i].y);
        __half2 hi = __floats2half2_rn(xr[i].z, xr[i].w);
        uint2 u;
        u.x = *(uint32_t*)&lo; u.y = *(uint32_t*)&hi;
        *(uint2*)(xo + i * 128) = u;
    }

    float sc[NEXP];
#pragma unroll
    for (int e = 0; e < NEXP; e++) {
        const float4* w = (const float4*)(gw + (size_t)e * DIM) + lane;
        float acc = 0.f;
#pragma unroll
        for (int i = 0; i < 8; i++) {
            float4 wv = w[i * 32];
            acc += xr[i].x * wv.x + xr[i].y * wv.y + xr[i].z * wv.z + xr[i].w * wv.w;
        }
#pragma unroll
        for (int o = 16; o > 0; o >>= 1) acc += __shfl_xor_sync(0xffffffffu, acc, o);
        sc[e] = 1.f / (1.f + __expf(-acc));
    }
    if (lane == 0) {
        float s[NEXP];
#pragma unroll
        for (int e = 0; e < NEXP; e++) s[e] = sc[e] + gbias[e];
        float gm[NGRP];
#pragma unroll
        for (int g = 0; g < NGRP; g++) {
            float m = s[g * GSZ];
#pragma unroll
            for (int j = 1; j < GSZ; j++) m = fmaxf(m, s[g * GSZ + j]);
            gm[g] = m;
        }
        int g1 = 0;
#pragma unroll
        for (int g = 1; g < NGRP; g++) if (gm[g] > gm[g1]) g1 = g;
        int g2 = -1;
#pragma unroll
        for (int g = 0; g < NGRP; g++) {
            if (g == g1) continue;
            if (g2 < 0 || gm[g] > gm[g2]) g2 = g;
        }
        float sm[NEXP];
#pragma unroll
        for (int e = 0; e < NEXP; e++) {
            int g = e / GSZ;
            sm[e] = (g == g1 || g == g2) ? s[e] : -1e30f;
        }
#pragma unroll
        for (int k = 0; k < TOPK; k++) {
            int best = 0; float bv = -1e38f;
#pragma unroll
            for (int e = 0; e < NEXP; e++) if (sm[e] > bv) { bv = sm[e]; best = e; }
            sm[best] = -1e38f;
            int pos = atomicAdd(&g_cnt[best], 1);
            g_tok[best][pos]  = t;
            g_slot[best][pos] = (unsigned char)k;
            g_wt[best][pos]   = sc[best];
        }
    }
}

#define FILL_ROW(stageu, R, srcp) do {                                        \
        uint32_t _rb = (stageu) + (uint32_t)(R) * 128;                        \
        int _e7 = (R) & 7;                                                    \
        cp16(_rb + (uint32_t)(((h4 + 0) ^ _e7) << 4), (srcp) + 0);            \
        cp16(_rb + (uint32_t)(((h4 + 1) ^ _e7) << 4), (srcp) + 8);            \
        cp16(_rb + (uint32_t)(((h4 + 2) ^ _e7) << 4), (srcp) + 16);           \
        cp16(_rb + (uint32_t)(((h4 + 3) ^ _e7) << 4), (srcp) + 24);           \
    } while (0)

// =====================================================================
// stage A: act = silu(X@W1^T)*(X@W3^T) — 128 thr, 64x64 warp tiles.
// z==NE1 blocks are riders converting W2/WS2 (scheduled last = drain tail).
// =====================================================================
__global__ __launch_bounds__(128, 2) void ffn_in_mma(
    const float* __restrict__ w2, const float* __restrict__ ws2)
{
    const int e = blockIdx.z;
    if (e == NE1) {
        const size_t total = WBIG + WSML;
        const size_t stride = (size_t)16 * 8 * 128 * 8;
        size_t base = ((size_t)blockIdx.x * 8 + blockIdx.y) * 1024 + (size_t)threadIdx.x * 8;
        for (size_t i = base; i < total; i += stride) {
            if (i < WBIG) cvt8(w2, g_w2h, i);
            else          cvt8(ws2 - WBIG, g_w2h, i);
        }
        return;
    }

    const int cnt = (e == NEXP) ? T_TOK : g_cnt[e];
    const int m0  = blockIdx.x * 128;
    if (m0 >= cnt) return;
    const int n0  = blockIdx.y * 64;

    extern __shared__ char smc[];
    const uint32_t sb = smem_u32(smc);
    const int tid = threadIdx.x;

    const int fr = tid >> 1, h4 = (tid & 1) * 4;
    const int hoff = (tid & 1) * 32;
    int ai0 = m0 + fr;       if (ai0 > cnt - 1) ai0 = cnt - 1;
    int ai1 = m0 + fr + 64;  if (ai1 > cnt - 1) ai1 = cnt - 1;
    const int tok0 = (e == NEXP) ? (m0 + fr)      : g_tok[e][ai0];
    const int tok1 = (e == NEXP) ? (m0 + fr + 64) : g_tok[e][ai1];
    const __half* s0 = g_xrh + (size_t)tok0 * DIM + hoff;
    const __half* s1 = g_xrh + (size_t)tok1 * DIM + hoff;
    const __half* s2 = g_w1h + (size_t)e * INTER * DIM + (size_t)(n0 + fr) * DIM + hoff;
    const __half* s3 = g_w3h + (size_t)e * INTER * DIM + (size_t)(n0 + fr) * DIM + hoff;

    const int lane = tid & 31, warp = tid >> 5;
    const int wm = warp >> 1, wn = warp & 1;
    const int gid = lane >> 2, tig = lane & 3;

    const uint32_t aRowB = (uint32_t)(lane & 15) * 128;
    const uint32_t ahi   = (uint32_t)(lane >> 4) * 16;
    const uint32_t bRowB = ((uint32_t)(lane & 7) + (uint32_t)((lane >> 4) & 1) * 8) * 128;
    const uint32_t bhi   = (uint32_t)((lane >> 3) & 1) * 16;
    const uint32_t sw    = (uint32_t)(lane & 7) * 16;

    float acc1[4][4][4], acc3[4][4][4];
#pragma unroll
    for (int i = 0; i < 4; i++)
#pragma unroll
        for (int j = 0; j < 4; j++)
#pragma unroll
            for (int k = 0; k < 4; k++) { acc1[i][j][k] = 0.f; acc3[i][j][k] = 0.f; }

#define ISSUE_A(kk) do {                                        \
        uint32_t _st = sb + (uint32_t)(((kk) % 3) * STG_BYTES); \
        const int _ko = (kk) * 64;                              \
        FILL_ROW(_st, fr,        s0 + _ko);                     \
        FILL_ROW(_st, fr + 64,   s1 + _ko);                     \
        FILL_ROW(_st, fr + 128,  s2 + _ko);                     \
        FILL_ROW(_st, fr + 192,  s3 + _ko);                     \
        CP_COMMIT();                                            \
    } while (0)

#define LOADF_A(b, ks) do {                                                      \
        const uint32_t _akx = ((uint32_t)((ks) * 32) + ahi) ^ sw;                \
        const uint32_t _bkx = ((uint32_t)((ks) * 32) + bhi) ^ sw;                \
        ldsm4(af[b][0], Ab + 0u * 2048 + _akx);                                  \
        ldsm4(af[b][1], Ab + 1u * 2048 + _akx);                                  \
        ldsm4(af[b][2], Ab + 2u * 2048 + _akx);                                  \
        ldsm4(af[b][3], Ab + 3u * 2048 + _akx);                                  \
        ldsm4(b1f[b][0], B1b + 0u * 2048 + _bkx);                                \
        ldsm4(b1f[b][1], B1b + 1u * 2048 + _bkx);                                \
        ldsm4(b3f[b][0], B3b + 0u * 2048 + _bkx);                                \
        ldsm4(b3f[b][1], B3b + 1u * 2048 + _bkx);                                \
    } while (0)

#define MMA_A(b) do {                                                            \
        _Pragma("unroll")                                                        \
        for (int ntp = 0; ntp < 2; ntp++)                                        \
            _Pragma("unroll")                                                    \
            for (int mt = 0; mt < 4; mt++) {                                     \
                mma_f16(acc1[mt][2 * ntp + 0], af[b][mt], b1f[b][ntp][0], b1f[b][ntp][1]); \
                mma_f16(acc1[mt][2 * ntp + 1], af[b][mt], b1f[b][ntp][2], b1f[b][ntp][3]); \
                mma_f16(acc3[mt][2 * ntp + 0], af[b][mt], b3f[b][ntp][0], b3f[b][ntp][1]); \
                mma_f16(acc3[mt][2 * ntp + 1], af[b][mt], b3f[b][ntp][2], b3f[b][ntp][3]); \
            }                                                                    \
    } while (0)

    ISSUE_A(0);
    ISSUE_A(1);

    uint32_t af[2][4][4], b1f[2][2][4], b3f[2][2][4];

    const int KITER = DIM / 64;
    for (int kk = 0; kk < KITER; kk++) {
        CP_WAIT1();
        __syncthreads();
        if (kk + 2 < KITER) { ISSUE_A(kk + 2); } else { CP_COMMIT(); }

        const uint32_t stage = sb + (uint32_t)((kk % 3) * STG_BYTES);
        const uint32_t Ab  = stage + (uint32_t)(wm * 64) * 128 + aRowB;
        const uint32_t B1b = stage + 16384u + (uint32_t)(wn * 32) * 128 + bRowB;
        const uint32_t B3b = stage + 24576u + (uint32_t)(wn * 32) * 128 + bRowB;

        LOADF_A(0, 0);
#pragma unroll
        for (int ks = 0; ks < 4; ks++) {
            if (ks < 3) LOADF_A((ks + 1) & 1, ks + 1);
            MMA_A(ks & 1);
        }
    }

#pragma unroll
    for (int mt = 0; mt < 4; mt++) {
#pragma unroll
        for (int h = 0; h < 2; h++) {
            const int m = m0 + wm * 64 + mt * 16 + gid + h * 8;
            if (m >= cnt) continue;
            __half* dst = &g_acth[((size_t)e * T_TOK + m) * INTER + n0 + wn * 32];
#pragma unroll
            for (int nt = 0; nt < 4; nt++) {
                float v0 = acc1[mt][nt][h * 2 + 0], u0 = acc3[mt][nt][h * 2 + 0];
                float v1 = acc1[mt][nt][h * 2 + 1], u1 = acc3[mt][nt][h * 2 + 1];
                *(__half2*)(dst + nt * 8 + tig * 2) =
                    __floats2half2_rn((v0 / (1.f + __expf(-v0))) * u0,
                                      (v1 / (1.f + __expf(-v1))) * u1);
            }
        }
    }
#undef ISSUE_A
#undef LOADF_A
#undef MMA_A
}

// =====================================================================
// stage B: y = act @ W2^T — 128 thr, 64x64 warp tiles, frag double-buffered
// =====================================================================
__global__ __launch_bounds__(128, 2) void ffn_out_mma(float* __restrict__ out)
{
    const int e   = blockIdx.z;
    const int cnt = (e == NEXP) ? T_TOK : g_cnt[e];
    const int m0  = blockIdx.x * 128;
    if (m0 >= cnt) return;
    const int n0  = blockIdx.y * 128;

    extern __shared__ char smc[];
    const uint32_t sb = smem_u32(smc);
    const int tid = threadIdx.x;

    const int fr = tid >> 1, h4 = (tid & 1) * 4;
    const int hoff = (tid & 1) * 32;
    int ai0 = m0 + fr;      if (ai0 > cnt - 1) ai0 = cnt - 1;
    int ai1 = m0 + fr + 64; if (ai1 > cnt - 1) ai1 = cnt - 1;
    const __half* s0 = g_acth + ((size_t)e * T_TOK + ai0) * INTER + hoff;
    const __half* s1 = g_acth + ((size_t)e * T_TOK + ai1) * INTER + hoff;
    const __half* s2 = g_w2h + (size_t)e * DIM * INTER + (size_t)(n0 + fr) * INTER + hoff;
    const __half* s3 = s2 + (size_t)64 * INTER;

    const int lane = tid & 31, warp = tid >> 5;
    const int wm = warp >> 1, wn = warp & 1;
    const int gid = lane >> 2, tig = lane & 3;

    const uint32_t aRowB = (uint32_t)(lane & 15) * 128;
    const uint32_t ahi   = (uint32_t)(lane >> 4) * 16;
    const uint32_t bRowB = ((uint32_t)(lane & 7) + (uint32_t)((lane >> 4) & 1) * 8) * 128;
    const uint32_t bhi   = (uint32_t)((lane >> 3) & 1) * 16;
    const uint32_t sw    = (uint32_t)(lane & 7) * 16;

    float acc[4][8][4];
#pragma unroll
    for (int i = 0; i < 4; i++)
#pragma unroll
        for (int j = 0; j < 8; j++)
#pragma unroll
            for (int k = 0; k < 4; k++) acc[i][j][k] = 0.f;

#define ISSUE_B(kk) do {                                        \
        uint32_t _st = sb + (uint32_t)(((kk) % 3) * STG_BYTES); \
        const int _ko = (kk) * 64;                              \
        FILL_ROW(_st, fr,        s0 + _ko);                     \
        FILL_ROW(_st, fr + 64,   s1 + _ko);                     \
        FILL_ROW(_st, fr + 128,  s2 + _ko);                     \
        FILL_ROW(_st, fr + 192,  s3 + _ko);                     \
        CP_COMMIT();                                            \
    } while (0)

#define LOADF_B(b, ks) do {                                                      \
        const uint32_t _akx = ((uint32_t)((ks) * 32) + ahi) ^ sw;                \
        const uint32_t _bkx = ((uint32_t)((ks) * 32) + bhi) ^ sw;                \
        ldsm4(af[b][0], Ab + 0u * 2048 + _akx);                                  \
        ldsm4(af[b][1], Ab + 1u * 2048 + _akx);                                  \
        ldsm4(af[b][2], Ab + 2u * 2048 + _akx);                                  \
        ldsm4(af[b][3], Ab + 3u * 2048 + _akx);                                  \
        ldsm4(bf[b][0], Bb + 0u * 2048 + _bkx);                                  \
        ldsm4(bf[b][1], Bb + 1u * 2048 + _bkx);                                  \
        ldsm4(bf[b][2], Bb + 2u * 2048 + _bkx);                                  \
        ldsm4(bf[b][3], Bb + 3u * 2048 + _bkx);                                  \
    } while (0)

#define MMA_B(b) do {                                                            \
        _Pragma("unroll")                                                        \
        for (int ntp = 0; ntp < 4; ntp++)                                        \
            _Pragma("unroll")                                                    \
            for (int mt = 0; mt < 4; mt++) {                                     \
                mma_f16(acc[mt][2 * ntp + 0], af[b][mt], bf[b][ntp][0], bf[b][ntp][1]); \
                mma_f16(acc[mt][2 * ntp + 1], af[b][mt], bf[b][ntp][2], bf[b][ntp][3]); \
            }                                                                    \
    } while (0)

    ISSUE_B(0);
    ISSUE_B(1);

    uint32_t af[2][4][4], bf[2][4][4];

    const int KITER = INTER / 64;
    for (int kk = 0; kk < KITER; kk++) {
        CP_WAIT1();
        __syncthreads();
        if (kk + 2 < KITER) { ISSUE_B(kk + 2); } else { CP_COMMIT(); }

        const uint32_t stage = sb + (uint32_t)((kk % 3) * STG_BYTES);
        const uint32_t Ab = stage + (uint32_t)(wm * 64) * 128 + aRowB;
        const uint32_t Bb = stage + 16384u + (uint32_t)(wn * 64) * 128 + bRowB;

        LOADF_B(0, 0);
#pragma unroll
        for (int ks = 0; ks < 4; ks++) {
            if (ks < 3) LOADF_B((ks + 1) & 1, ks + 1);
            MMA_B(ks & 1);
        }
    }

#pragma unroll
    for (int mt = 0; mt < 4; mt++) {
#pragma unroll
        for (int h = 0; h < 2; h++) {
            const int m = m0 + wm * 64 + mt * 16 + gid + h * 8;
            if (m >= cnt) continue;
            float wt = 1.f;
            float* dst;
            if (e == NEXP) {
                dst = out + (size_t)m * DIM + n0 + wn * 64;
            } else {
                const int tokm = g_tok[e][m];
                const int sl   = g_slot[e][m];
                wt             = g_wt[e][m];
                dst = &g_ybuf[sl][(size_t)tokm * DIM + n0 + wn * 64];
            }
#pragma unroll
            for (int nt = 0; nt < 8; nt++) {
                *(float2*)(dst + nt * 8 + tig * 2) =
                    make_float2(acc[mt][nt][h * 2 + 0] * wt,
                                acc[mt][nt][h * 2 + 1] * wt);
            }
        }
    }
#undef ISSUE_B
#undef LOADF_B
#undef MMA_B
}

// ---------------- reduce: out += sum ybuf; re-zero g_cnt for next replay ----------------
__global__ void reduce_kernel(float* __restrict__ out) {
    if (blockIdx.x == 0 && threadIdx.x < NEXP) g_cnt[threadIdx.x] = 0;
    size_t idx = ((size_t)blockIdx.x * blockDim.x + threadIdx.x) * 4;
    if (idx < (size_t)T_TOK * DIM) {
        float4 o = *(float4*)(out + idx);
        float4 a = *(const float4*)(&g_ybuf[0][idx]);
        float4 b = *(const float4*)(&g_ybuf[1][idx]);
        float4 c = *(const float4*)(&g_ybuf[2][idx]);
        float4 d = *(const float4*)(&g_ybuf[3][idx]);
        o.x += a.x + b.x + c.x + d.x;
        o.y += a.y + b.y + c.y + d.y;
        o.z += a.z + b.z + c.z + d.z;
        o.w += a.w + b.w + c.w + d.w;
        *(float4*)(out + idx) = o;
    }
}

// ---------------- launch ----------------
extern "C" void kernel_launch(void* const* d_in, const int* in_sizes, int n_in,
                              void* d_out, int out_size) {
    const float* x   = (const float*)d_in[0];
    const float* gw  = (const float*)d_in[1];
    const float* gb  = (const float*)d_in[2];
    const float* w1  = (const float*)d_in[3];
    const float* w2  = (const float*)d_in[4];
    const float* w3  = (const float*)d_in[5];
    const float* ws1 = (const float*)d_in[6];
    const float* ws2 = (const float*)d_in[7];
    const float* ws3 = (const float*)d_in[8];
    float* out = (float*)d_out;

    cudaFuncSetAttribute(ffn_in_mma,  cudaFuncAttributeMaxDynamicSharedMemorySize, SMEM_BYTES);
    cudaFuncSetAttribute(ffn_out_mma, cudaFuncAttributeMaxDynamicSharedMemorySize, SMEM_BYTES);

    // gate (256 blocks) + convert w1/w3/ws1/ws3 (1088 blocks, MLP=8)
    prep_kernel<<<1344, 256>>>(x, gw, gb, w1, w3, ws1, ws3);
    ffn_in_mma<<<dim3(T_TOK / 128, INTER / 64, NE1 + 1), 128, SMEM_BYTES>>>(w2, ws2);
    ffn_out_mma<<<dim3(T_TOK / 128, DIM / 128, NE1), 128, SMEM_BYTES>>>(out);
    reduce_kernel<<<(T_TOK * DIM / 4 + 255) / 256, 256>>>(out);
}